// round 10
// baseline (speedup 1.0000x reference)
#include <cuda_runtime.h>
#include <cuda_fp16.h>
#include <cstdint>
#include <cstddef>

// ---------------------------------------------------------------------------
// Critic_Mix fused kernel (round 9): fp16 m16n8k16 mma.sync, BM=64, 256 thr,
// 2 CTAs/SM. R9: mix accumulator packed as __half2 (frees 16 regs) funding a
// 2-stage LDSM fragment pipeline; bias load hoisted before mid barrier;
// epilogue store addresses strength-reduced (row&7 == lq).
// ---------------------------------------------------------------------------

#define THREADS   256
#define BM        64
#define BATCH     262144
#define NBLK      (BATCH / BM)

#define ACT_B      16384                 // 64 rows x 256B (128 fp16)
#define WBUF_B     32768                 // 128 rows x 256B fp16
#define WBUF_OFF   (5 * ACT_B)           // 81920
#define BIAS_OFF   (WBUF_OFF + WBUF_B)   // 114688
#define SMEM_BYTES (BIAS_OFF + 1024)     // 115712 -> 2 CTAs/SM

__device__ uint4 g_wimg[30 * 2048];
__device__ float g_bimg[30 * 128];

struct Params {
    const float* x;
    const float* u;
    const float* mixf;
    const float* P;
    const float* W[2][3];
    const float* Bb[2][3];
    const float* W4[2];
    const float* b4[2];
    const float* tW[2][3];
    const float* tb[2][3];
    float*       out;
};

__device__ __forceinline__ uint32_t s2u(const void* p) {
    uint32_t a;
    asm("{ .reg .u64 t; cvta.to.shared.u64 t, %1; cvt.u32.u64 %0, t; }"
        : "=r"(a) : "l"(p));
    return a;
}
__device__ __forceinline__ void ldsm4(uint32_t* r, uint32_t addr) {
    asm volatile("ldmatrix.sync.aligned.m8n8.x4.shared.b16 {%0,%1,%2,%3}, [%4];"
                 : "=r"(r[0]), "=r"(r[1]), "=r"(r[2]), "=r"(r[3]) : "r"(addr));
}
__device__ __forceinline__ void mma16(float* c, const uint32_t* a,
                                      uint32_t b0, uint32_t b1) {
    asm volatile(
        "mma.sync.aligned.m16n8k16.row.col.f32.f16.f16.f32 "
        "{%0,%1,%2,%3}, {%4,%5,%6,%7}, {%8,%9}, {%0,%1,%2,%3};"
        : "+f"(c[0]), "+f"(c[1]), "+f"(c[2]), "+f"(c[3])
        : "r"(a[0]), "r"(a[1]), "r"(a[2]), "r"(a[3]), "r"(b0), "r"(b1));
}
__device__ __forceinline__ void cpasync16(uint32_t dst, const void* src) {
    asm volatile("cp.async.cg.shared.global [%0], [%1], 16;"
                 :: "r"(dst), "l"(src) : "memory");
}

// ---------------- preprocessing kernel ----------------
__global__ void prep_kernel(Params p) {
    const int idx = blockIdx.x * 256 + threadIdx.x;
    if (idx < 30 * 2048) {
        const int img = idx >> 11, rem = idx & 2047;
        const int n = rem >> 4, ch = rem & 15;
        const int h = img / 15, rr = img % 15, L = rr / 5, s = rr % 5;
        const int O = (L == 2) ? 64 : 128;
        uint4 o = make_uint4(0u, 0u, 0u, 0u);
        if (n < O) {
            const float* W = (s == 4) ? p.W[h][L]
                                      : p.tW[h][L] + (size_t)s * O * 128;
            const float4 v0 = *reinterpret_cast<const float4*>(W + (size_t)n * 128 + ch * 8);
            const float4 v1 = *reinterpret_cast<const float4*>(W + (size_t)n * 128 + ch * 8 + 4);
            __half2 t0 = __floats2half2_rn(v0.x, v0.y);
            __half2 t1 = __floats2half2_rn(v0.z, v0.w);
            __half2 t2 = __floats2half2_rn(v1.x, v1.y);
            __half2 t3 = __floats2half2_rn(v1.z, v1.w);
            o.x = *reinterpret_cast<uint32_t*>(&t0);
            o.y = *reinterpret_cast<uint32_t*>(&t1);
            o.z = *reinterpret_cast<uint32_t*>(&t2);
            o.w = *reinterpret_cast<uint32_t*>(&t3);
        }
        g_wimg[img * 2048 + n * 16 + (ch ^ (n & 7))] = o;
    } else if (idx < 30 * 2048 + 960) {
        const int b = idx - 30 * 2048;
        const int img = b >> 5, q = b & 31;
        const int h = img / 15, rr = img % 15, L = rr / 5, s = rr % 5;
        const int O = (L == 2) ? 64 : 128;
        const float* B = (s == 4) ? p.Bb[h][L] : p.tb[h][L] + s * O;
        const int o = q * 4;
        float4 v;
        v.x = (o + 0 < O) ? B[o + 0] : 0.f;
        v.y = (o + 1 < O) ? B[o + 1] : 0.f;
        v.z = (o + 2 < O) ? B[o + 2] : 0.f;
        v.w = (o + 3 < O) ? B[o + 3] : 0.f;
        *reinterpret_cast<float4*>(g_bimg + img * 128 + o) = v;
    }
}

// ---------------- main kernel ----------------
__device__ __forceinline__ void prefetch_img(uint32_t wbuf_u, uint32_t bias_u,
                                             int img, int bslot, int tid) {
    const uint4* src = g_wimg + img * 2048;
    const int nv = (((img % 15) / 5) == 2) ? 4 : 8;   // L=2: 16KB only
    #pragma unroll
    for (int i = 0; i < 8; i++)
        if (i < nv)
            cpasync16(wbuf_u + (uint32_t)(tid + i * 256) * 16, src + tid + i * 256);
    if (tid < 32)
        cpasync16(bias_u + (uint32_t)bslot * 512 + tid * 16,
                  reinterpret_cast<const float4*>(g_bimg + img * 128) + tid);
    asm volatile("cp.async.commit_group;" ::: "memory");
}

__global__ void __launch_bounds__(THREADS, 2)
critic_main(Params p) {
    extern __shared__ char smem[];
    const uint32_t sbase  = s2u(smem);
    const uint32_t wbuf_u = sbase + WBUF_OFF;
    const uint32_t bias_u = sbase + BIAS_OFF;
    float* biasf = reinterpret_cast<float*>(smem + BIAS_OFF);

    const int tid  = threadIdx.x;
    const int lane = tid & 31;
    const int wid  = tid >> 5;
    const int wm   = wid & 1;           // 2 warps over m
    const int wn   = wid >> 1;          // 4 warps over n
    const int mbase = wm * 32;
    const int nbase = wn * 32;
    const int lq = lane >> 2, lr = lane & 3;
    const int r8 = lane & 7, sel = lane >> 3;
    const int row0 = blockIdx.x * BM;
    const bool lowN = (wn < 2);

    const int rA0 = mbase + (sel & 1) * 8 + r8;
    const int rB0 = nbase + (sel >> 1) * 8 + r8;
    const uint32_t eA4 = (uint32_t)(((sel >> 1) ^ r8) << 4);
    const uint32_t eB4 = (uint32_t)(((sel & 1) ^ r8) << 4);
    const uint32_t aoff0 = (uint32_t)rA0 * 256;
    const uint32_t aoff1 = aoff0 + 16 * 256;
    const uint32_t bb0 = wbuf_u + (uint32_t)rB0 * 256;
    const uint32_t bb1 = bb0 + 16 * 256;

    // epilogue store offsets: row = mbase+mt*16+lq+c2*8 -> row&7 == lq
    // addr = outb + rbase + mt*4096 + c2*2048 + coff[nt]
    const uint32_t rbase = (uint32_t)(mbase + lq) * 256;
    uint32_t coff[4];
    #pragma unroll
    for (int nt = 0; nt < 4; nt++)
        coff[nt] = ((uint32_t)((((nbase >> 3) + nt) ^ lq) << 4)) + (uint32_t)lr * 4;

    const float m = __ldg(p.mixf);
    const float inv_m = 1.0f - m;
    float Pk[4];
    #pragma unroll
    for (int k = 0; k < 4; k++) Pk[k] = __ldg(p.P + k);

    prefetch_img(wbuf_u, bias_u, 0, 0, tid);

    for (int h = 0; h < 2; h++) {
        // ---- xu -> act buffer 4 (fp16, swizzled) ----
        {
            char* dst = smem + 4 * ACT_B;
            #pragma unroll
            for (int i = tid; i < BM * 16; i += THREADS) {
                const int r = i >> 4, ch = i & 15;
                float4 v0, v1;
                if (ch < 12) {
                    const float* src = p.x + (size_t)(row0 + r) * 96 + ch * 8;
                    v0 = *reinterpret_cast<const float4*>(src);
                    v1 = *reinterpret_cast<const float4*>(src + 4);
                } else {
                    const float* src = p.u + (size_t)(row0 + r) * 32 + (ch - 12) * 8;
                    v0 = *reinterpret_cast<const float4*>(src);
                    v1 = *reinterpret_cast<const float4*>(src + 4);
                }
                __half2 t0 = __floats2half2_rn(v0.x, v0.y);
                __half2 t1 = __floats2half2_rn(v0.z, v0.w);
                __half2 t2 = __floats2half2_rn(v1.x, v1.y);
                __half2 t3 = __floats2half2_rn(v1.z, v1.w);
                uint4 o;
                o.x = *reinterpret_cast<uint32_t*>(&t0);
                o.y = *reinterpret_cast<uint32_t*>(&t1);
                o.z = *reinterpret_cast<uint32_t*>(&t2);
                o.w = *reinterpret_cast<uint32_t*>(&t3);
                *reinterpret_cast<uint4*>(dst + r * 256 + ((ch ^ (r & 7)) << 4)) = o;
            }
        }

        __half2 mix2[2][4][2];                    // packed mix accumulator
        for (int t = 0; t < 15; t++) {
            const int g = h * 15 + t;
            const int L = t / 5, s = t % 5;
            const bool is_main = (s == 4);
            const bool active  = (L < 2) || lowN;
            if (s == 0) {
                const __half2 z = __floats2half2_rn(0.f, 0.f);
                #pragma unroll
                for (int mt = 0; mt < 2; mt++)
                    #pragma unroll
                    for (int nt = 0; nt < 4; nt++) {
                        mix2[mt][nt][0] = z; mix2[mt][nt][1] = z;
                    }
            }

            asm volatile("cp.async.wait_group 0;" ::: "memory");
            __syncthreads();

            float acc[2][4][4];
            #pragma unroll
            for (int mt = 0; mt < 2; mt++)
                #pragma unroll
                for (int nt = 0; nt < 4; nt++)
                    #pragma unroll
                    for (int c = 0; c < 4; c++) acc[mt][nt][c] = 0.f;

            if (active) {
                const int inb = (L == 0) ? 4 : (is_main ? 4 : s);
                const uint32_t ab0 = sbase + (uint32_t)inb * ACT_B + aoff0;
                const uint32_t ab1 = sbase + (uint32_t)inb * ACT_B + aoff1;

                // 2-stage fragment pipeline
                uint32_t fa0[2][4], fa1[2][4], fb0[2][4], fb1[2][4];
                ldsm4(fa0[0], ab0 + eA4);
                ldsm4(fa1[0], ab1 + eA4);
                ldsm4(fb0[0], bb0 + eB4);
                ldsm4(fb1[0], bb1 + eB4);
                #pragma unroll
                for (int j = 0; j < 8; j++) {
                    const int cur = j & 1, nxt = cur ^ 1;
                    if (j < 7) {
                        const uint32_t tA = ((uint32_t)((j + 1) << 5)) ^ eA4;
                        const uint32_t tB = ((uint32_t)((j + 1) << 5)) ^ eB4;
                        ldsm4(fa0[nxt], ab0 + tA);
                        ldsm4(fa1[nxt], ab1 + tA);
                        ldsm4(fb0[nxt], bb0 + tB);
                        ldsm4(fb1[nxt], bb1 + tB);
                    }
                    mma16(acc[0][0], fa0[cur], fb0[cur][0], fb0[cur][1]);
                    mma16(acc[0][1], fa0[cur], fb0[cur][2], fb0[cur][3]);
                    mma16(acc[0][2], fa0[cur], fb1[cur][0], fb1[cur][1]);
                    mma16(acc[0][3], fa0[cur], fb1[cur][2], fb1[cur][3]);
                    mma16(acc[1][0], fa1[cur], fb0[cur][0], fb0[cur][1]);
                    mma16(acc[1][1], fa1[cur], fb0[cur][2], fb0[cur][3]);
                    mma16(acc[1][2], fa1[cur], fb1[cur][0], fb1[cur][1]);
                    mma16(acc[1][3], fa1[cur], fb1[cur][2], fb1[cur][3]);
                }
            }

            // bias for THIS stream (slot g&1 stable since top barrier):
            // load before the barrier so LDS overlaps the drain.
            float bias[4][2];
            {
                const float* bs = biasf + (g & 1) * 128;
                #pragma unroll
                for (int nt = 0; nt < 4; nt++) {
                    bias[nt][0] = bs[nbase + nt * 8 + lr * 2 + 0];
                    bias[nt][1] = bs[nbase + nt * 8 + lr * 2 + 1];
                }
            }

            __syncthreads();    // wbuf + act reads done

            prefetch_img(wbuf_u, bias_u, (g + 1) % 30, (g + 1) & 1, tid);

            if (active) {
                const float sc = is_main ? inv_m : (m * Pk[s]);
                const bool do_store = is_main || (L < 2);
                char* outb = smem + (is_main ? 4 : s) * ACT_B;
                #pragma unroll
                for (int mt = 0; mt < 2; mt++)
                    #pragma unroll
                    for (int nt = 0; nt < 4; nt++)
                        #pragma unroll
                        for (int c2 = 0; c2 < 2; c2++) {
                            const float v0 = acc[mt][nt][c2 * 2 + 0] + bias[nt][0];
                            const float v1 = acc[mt][nt][c2 * 2 + 1] + bias[nt][1];
                            float o0, o1;
                            if (!is_main) {
                                float2 mf = __half22float2(mix2[mt][nt][c2]);
                                mf.x = fmaf(sc, v0, mf.x);
                                mf.y = fmaf(sc, v1, mf.y);
                                mix2[mt][nt][c2] = __floats2half2_rn(mf.x, mf.y);
                                o0 = v0; o1 = v1;
                            } else {
                                o0 = fmaf(sc, v0, __low2float(mix2[mt][nt][c2]));
                                o1 = fmaf(sc, v1, __high2float(mix2[mt][nt][c2]));
                            }
                            if (do_store) {
                                __half2 hv = __floats2half2_rn(fmaxf(o0, 0.f),
                                                               fmaxf(o1, 0.f));
                                *reinterpret_cast<uint32_t*>(
                                    outb + rbase + mt * 4096 + c2 * 2048 + coff[nt])
                                    = *reinterpret_cast<uint32_t*>(&hv);
                            }
                        }
            }
        }

        __syncthreads();
        // ---- final layer: out = h3 . W4 + b4 ----
        if (tid < BM) {
            float sum = __ldg(p.b4[h]);
            const float* W4 = p.W4[h];
            const char* hb = smem + 4 * ACT_B;
            #pragma unroll
            for (int k2 = 0; k2 < 64; k2++) {
                const __half hv = *reinterpret_cast<const __half*>(
                    hb + tid * 256 + (((k2 >> 3) ^ (tid & 7)) << 4) + (k2 & 7) * 2);
                sum = fmaf(__half2float(hv), __ldg(W4 + k2), sum);
            }
            p.out[(size_t)h * BATCH + row0 + tid] = sum;
        }
        __syncthreads();
    }
}

extern "C" void kernel_launch(void* const* d_in, const int* in_sizes, int n_in,
                              void* d_out, int out_size) {
    (void)in_sizes; (void)n_in; (void)out_size;
    Params p;
    p.x    = (const float*)d_in[0];
    p.u    = (const float*)d_in[1];
    p.mixf = (const float*)d_in[2];
    p.P    = (const float*)d_in[3];
    for (int h = 0; h < 2; h++) {
        const int base = 4 + h * 8;
        p.W[h][0]  = (const float*)d_in[base + 0];
        p.Bb[h][0] = (const float*)d_in[base + 1];
        p.W[h][1]  = (const float*)d_in[base + 2];
        p.Bb[h][1] = (const float*)d_in[base + 3];
        p.W[h][2]  = (const float*)d_in[base + 4];
        p.Bb[h][2] = (const float*)d_in[base + 5];
        p.W4[h]    = (const float*)d_in[base + 6];
        p.b4[h]    = (const float*)d_in[base + 7];
        const int tbase = 20 + h * 6;
        p.tW[h][0] = (const float*)d_in[tbase + 0];
        p.tb[h][0] = (const float*)d_in[tbase + 1];
        p.tW[h][1] = (const float*)d_in[tbase + 2];
        p.tb[h][1] = (const float*)d_in[tbase + 3];
        p.tW[h][2] = (const float*)d_in[tbase + 4];
        p.tb[h][2] = (const float*)d_in[tbase + 5];
    }
    p.out = (float*)d_out;

    prep_kernel<<<(30 * 2048 + 960 + 255) / 256, 256>>>(p);
    cudaFuncSetAttribute(critic_main,
                         cudaFuncAttributeMaxDynamicSharedMemorySize, SMEM_BYTES);
    critic_main<<<NBLK, THREADS, SMEM_BYTES>>>(p);
}

// round 11
// speedup vs baseline: 1.6195x; 1.6195x over previous
#include <cuda_runtime.h>
#include <cuda_fp16.h>
#include <cstdint>
#include <cstddef>

// ---------------------------------------------------------------------------
// Critic_Mix fused kernel (round 10): R8 structure restored (fp32 mix,
// single-stage k-loop, 2 CTAs/SM) + two register-neutral tweaks from R9:
// bias LDS hoisted before the mid barrier, strength-reduced epilogue stores.
// ---------------------------------------------------------------------------

#define THREADS   256
#define BM        64
#define BATCH     262144
#define NBLK      (BATCH / BM)

#define ACT_B      16384                 // 64 rows x 256B (128 fp16)
#define WBUF_B     32768                 // 128 rows x 256B fp16
#define WBUF_OFF   (5 * ACT_B)           // 81920
#define BIAS_OFF   (WBUF_OFF + WBUF_B)   // 114688
#define SMEM_BYTES (BIAS_OFF + 1024)     // 115712 -> 2 CTAs/SM

__device__ uint4 g_wimg[30 * 2048];
__device__ float g_bimg[30 * 128];

struct Params {
    const float* x;
    const float* u;
    const float* mixf;
    const float* P;
    const float* W[2][3];
    const float* Bb[2][3];
    const float* W4[2];
    const float* b4[2];
    const float* tW[2][3];
    const float* tb[2][3];
    float*       out;
};

__device__ __forceinline__ uint32_t s2u(const void* p) {
    uint32_t a;
    asm("{ .reg .u64 t; cvta.to.shared.u64 t, %1; cvt.u32.u64 %0, t; }"
        : "=r"(a) : "l"(p));
    return a;
}
__device__ __forceinline__ void ldsm4(uint32_t* r, uint32_t addr) {
    asm volatile("ldmatrix.sync.aligned.m8n8.x4.shared.b16 {%0,%1,%2,%3}, [%4];"
                 : "=r"(r[0]), "=r"(r[1]), "=r"(r[2]), "=r"(r[3]) : "r"(addr));
}
__device__ __forceinline__ void mma16(float* c, const uint32_t* a,
                                      uint32_t b0, uint32_t b1) {
    asm volatile(
        "mma.sync.aligned.m16n8k16.row.col.f32.f16.f16.f32 "
        "{%0,%1,%2,%3}, {%4,%5,%6,%7}, {%8,%9}, {%0,%1,%2,%3};"
        : "+f"(c[0]), "+f"(c[1]), "+f"(c[2]), "+f"(c[3])
        : "r"(a[0]), "r"(a[1]), "r"(a[2]), "r"(a[3]), "r"(b0), "r"(b1));
}
__device__ __forceinline__ void cpasync16(uint32_t dst, const void* src) {
    asm volatile("cp.async.cg.shared.global [%0], [%1], 16;"
                 :: "r"(dst), "l"(src) : "memory");
}

// ---------------- preprocessing kernel ----------------
__global__ void prep_kernel(Params p) {
    const int idx = blockIdx.x * 256 + threadIdx.x;
    if (idx < 30 * 2048) {
        const int img = idx >> 11, rem = idx & 2047;
        const int n = rem >> 4, ch = rem & 15;
        const int h = img / 15, rr = img % 15, L = rr / 5, s = rr % 5;
        const int O = (L == 2) ? 64 : 128;
        uint4 o = make_uint4(0u, 0u, 0u, 0u);
        if (n < O) {
            const float* W = (s == 4) ? p.W[h][L]
                                      : p.tW[h][L] + (size_t)s * O * 128;
            const float4 v0 = *reinterpret_cast<const float4*>(W + (size_t)n * 128 + ch * 8);
            const float4 v1 = *reinterpret_cast<const float4*>(W + (size_t)n * 128 + ch * 8 + 4);
            __half2 t0 = __floats2half2_rn(v0.x, v0.y);
            __half2 t1 = __floats2half2_rn(v0.z, v0.w);
            __half2 t2 = __floats2half2_rn(v1.x, v1.y);
            __half2 t3 = __floats2half2_rn(v1.z, v1.w);
            o.x = *reinterpret_cast<uint32_t*>(&t0);
            o.y = *reinterpret_cast<uint32_t*>(&t1);
            o.z = *reinterpret_cast<uint32_t*>(&t2);
            o.w = *reinterpret_cast<uint32_t*>(&t3);
        }
        g_wimg[img * 2048 + n * 16 + (ch ^ (n & 7))] = o;
    } else if (idx < 30 * 2048 + 960) {
        const int b = idx - 30 * 2048;
        const int img = b >> 5, q = b & 31;
        const int h = img / 15, rr = img % 15, L = rr / 5, s = rr % 5;
        const int O = (L == 2) ? 64 : 128;
        const float* B = (s == 4) ? p.Bb[h][L] : p.tb[h][L] + s * O;
        const int o = q * 4;
        float4 v;
        v.x = (o + 0 < O) ? B[o + 0] : 0.f;
        v.y = (o + 1 < O) ? B[o + 1] : 0.f;
        v.z = (o + 2 < O) ? B[o + 2] : 0.f;
        v.w = (o + 3 < O) ? B[o + 3] : 0.f;
        *reinterpret_cast<float4*>(g_bimg + img * 128 + o) = v;
    }
}

// ---------------- main kernel ----------------
__device__ __forceinline__ void prefetch_img(uint32_t wbuf_u, uint32_t bias_u,
                                             int img, int bslot, int tid) {
    const uint4* src = g_wimg + img * 2048;
    const int nv = (((img % 15) / 5) == 2) ? 4 : 8;   // L=2: 16KB only
    #pragma unroll
    for (int i = 0; i < 8; i++)
        if (i < nv)
            cpasync16(wbuf_u + (uint32_t)(tid + i * 256) * 16, src + tid + i * 256);
    if (tid < 32)
        cpasync16(bias_u + (uint32_t)bslot * 512 + tid * 16,
                  reinterpret_cast<const float4*>(g_bimg + img * 128) + tid);
    asm volatile("cp.async.commit_group;" ::: "memory");
}

__global__ void __launch_bounds__(THREADS, 2)
critic_main(Params p) {
    extern __shared__ char smem[];
    const uint32_t sbase  = s2u(smem);
    const uint32_t wbuf_u = sbase + WBUF_OFF;
    const uint32_t bias_u = sbase + BIAS_OFF;
    float* biasf = reinterpret_cast<float*>(smem + BIAS_OFF);

    const int tid  = threadIdx.x;
    const int lane = tid & 31;
    const int wid  = tid >> 5;
    const int wm   = wid & 1;           // 2 warps over m
    const int wn   = wid >> 1;          // 4 warps over n
    const int mbase = wm * 32;
    const int nbase = wn * 32;
    const int lq = lane >> 2, lr = lane & 3;
    const int r8 = lane & 7, sel = lane >> 3;
    const int row0 = blockIdx.x * BM;
    const bool lowN = (wn < 2);

    const int rA0 = mbase + (sel & 1) * 8 + r8;
    const int rB0 = nbase + (sel >> 1) * 8 + r8;
    const uint32_t eA4 = (uint32_t)(((sel >> 1) ^ r8) << 4);
    const uint32_t eB4 = (uint32_t)(((sel & 1) ^ r8) << 4);
    const uint32_t aoff0 = (uint32_t)rA0 * 256;
    const uint32_t aoff1 = aoff0 + 16 * 256;
    const uint32_t bb0 = wbuf_u + (uint32_t)rB0 * 256;
    const uint32_t bb1 = bb0 + 16 * 256;

    // epilogue store addressing: row = mbase+mt*16+lq+c2*8 -> row&7 == lq
    // addr = outb + rbase + mt*4096 + c2*2048 + coff[nt]
    const uint32_t rbase = (uint32_t)(mbase + lq) * 256;
    uint32_t coff[4];
    #pragma unroll
    for (int nt = 0; nt < 4; nt++)
        coff[nt] = ((uint32_t)((((nbase >> 3) + nt) ^ lq) << 4)) + (uint32_t)lr * 4;

    const float m = __ldg(p.mixf);
    const float inv_m = 1.0f - m;
    float Pk[4];
    #pragma unroll
    for (int k = 0; k < 4; k++) Pk[k] = __ldg(p.P + k);

    prefetch_img(wbuf_u, bias_u, 0, 0, tid);

    for (int h = 0; h < 2; h++) {
        // ---- xu -> act buffer 4 (fp16, swizzled) ----
        {
            char* dst = smem + 4 * ACT_B;
            #pragma unroll
            for (int i = tid; i < BM * 16; i += THREADS) {
                const int r = i >> 4, ch = i & 15;
                float4 v0, v1;
                if (ch < 12) {
                    const float* src = p.x + (size_t)(row0 + r) * 96 + ch * 8;
                    v0 = *reinterpret_cast<const float4*>(src);
                    v1 = *reinterpret_cast<const float4*>(src + 4);
                } else {
                    const float* src = p.u + (size_t)(row0 + r) * 32 + (ch - 12) * 8;
                    v0 = *reinterpret_cast<const float4*>(src);
                    v1 = *reinterpret_cast<const float4*>(src + 4);
                }
                __half2 t0 = __floats2half2_rn(v0.x, v0.y);
                __half2 t1 = __floats2half2_rn(v0.z, v0.w);
                __half2 t2 = __floats2half2_rn(v1.x, v1.y);
                __half2 t3 = __floats2half2_rn(v1.z, v1.w);
                uint4 o;
                o.x = *reinterpret_cast<uint32_t*>(&t0);
                o.y = *reinterpret_cast<uint32_t*>(&t1);
                o.z = *reinterpret_cast<uint32_t*>(&t2);
                o.w = *reinterpret_cast<uint32_t*>(&t3);
                *reinterpret_cast<uint4*>(dst + r * 256 + ((ch ^ (r & 7)) << 4)) = o;
            }
        }

        float mix[2][4][4];
        for (int t = 0; t < 15; t++) {
            const int g = h * 15 + t;
            const int L = t / 5, s = t % 5;
            const bool is_main = (s == 4);
            const bool active  = (L < 2) || lowN;
            if (s == 0) {
                #pragma unroll
                for (int mt = 0; mt < 2; mt++)
                    #pragma unroll
                    for (int nt = 0; nt < 4; nt++)
                        #pragma unroll
                        for (int c = 0; c < 4; c++) mix[mt][nt][c] = 0.f;
            }

            asm volatile("cp.async.wait_group 0;" ::: "memory");
            __syncthreads();

            float acc[2][4][4];
            #pragma unroll
            for (int mt = 0; mt < 2; mt++)
                #pragma unroll
                for (int nt = 0; nt < 4; nt++)
                    #pragma unroll
                    for (int c = 0; c < 4; c++) acc[mt][nt][c] = 0.f;

            if (active) {
                const int inb = (L == 0) ? 4 : (is_main ? 4 : s);
                const uint32_t ab0 = sbase + (uint32_t)inb * ACT_B + aoff0;
                const uint32_t ab1 = sbase + (uint32_t)inb * ACT_B + aoff1;

                #pragma unroll
                for (int j = 0; j < 8; j++) {
                    const uint32_t tA = ((uint32_t)(j << 5)) ^ eA4;
                    const uint32_t tB = ((uint32_t)(j << 5)) ^ eB4;
                    uint32_t fa0[4], fa1[4], fb0[4], fb1[4];
                    ldsm4(fa0, ab0 + tA);
                    ldsm4(fa1, ab1 + tA);
                    ldsm4(fb0, bb0 + tB);
                    ldsm4(fb1, bb1 + tB);
                    mma16(acc[0][0], fa0, fb0[0], fb0[1]);
                    mma16(acc[0][1], fa0, fb0[2], fb0[3]);
                    mma16(acc[0][2], fa0, fb1[0], fb1[1]);
                    mma16(acc[0][3], fa0, fb1[2], fb1[3]);
                    mma16(acc[1][0], fa1, fb0[0], fb0[1]);
                    mma16(acc[1][1], fa1, fb0[2], fb0[3]);
                    mma16(acc[1][2], fa1, fb1[0], fb1[1]);
                    mma16(acc[1][3], fa1, fb1[2], fb1[3]);
                }
            }

            // bias for THIS stream: slot g&1 is stable since the top barrier,
            // so load before the mid barrier (LDS overlaps barrier drain).
            float bias[4][2];
            {
                const float* bs = biasf + (g & 1) * 128;
                #pragma unroll
                for (int nt = 0; nt < 4; nt++) {
                    bias[nt][0] = bs[nbase + nt * 8 + lr * 2 + 0];
                    bias[nt][1] = bs[nbase + nt * 8 + lr * 2 + 1];
                }
            }

            __syncthreads();    // wbuf + act reads done

            prefetch_img(wbuf_u, bias_u, (g + 1) % 30, (g + 1) & 1, tid);

            if (active) {
                const float sc = is_main ? inv_m : (m * Pk[s]);
                const bool do_store = is_main || (L < 2);
                char* outb = smem + (is_main ? 4 : s) * ACT_B;
                #pragma unroll
                for (int mt = 0; mt < 2; mt++)
                    #pragma unroll
                    for (int nt = 0; nt < 4; nt++)
                        #pragma unroll
                        for (int c2 = 0; c2 < 2; c2++) {
                            const float v0 = acc[mt][nt][c2 * 2 + 0] + bias[nt][0];
                            const float v1 = acc[mt][nt][c2 * 2 + 1] + bias[nt][1];
                            float o0, o1;
                            if (!is_main) {
                                mix[mt][nt][c2 * 2 + 0] = fmaf(sc, v0, mix[mt][nt][c2 * 2 + 0]);
                                mix[mt][nt][c2 * 2 + 1] = fmaf(sc, v1, mix[mt][nt][c2 * 2 + 1]);
                                o0 = v0; o1 = v1;
                            } else {
                                o0 = fmaf(sc, v0, mix[mt][nt][c2 * 2 + 0]);
                                o1 = fmaf(sc, v1, mix[mt][nt][c2 * 2 + 1]);
                            }
                            if (do_store) {
                                __half2 hv = __floats2half2_rn(fmaxf(o0, 0.f),
                                                               fmaxf(o1, 0.f));
                                *reinterpret_cast<uint32_t*>(
                                    outb + rbase + mt * 4096 + c2 * 2048 + coff[nt])
                                    = *reinterpret_cast<uint32_t*>(&hv);
                            }
                        }
            }
        }

        __syncthreads();
        // ---- final layer: out = h3 . W4 + b4 ----
        if (tid < BM) {
            float sum = __ldg(p.b4[h]);
            const float* W4 = p.W4[h];
            const char* hb = smem + 4 * ACT_B;
            #pragma unroll
            for (int k2 = 0; k2 < 64; k2++) {
                const __half hv = *reinterpret_cast<const __half*>(
                    hb + tid * 256 + (((k2 >> 3) ^ (tid & 7)) << 4) + (k2 & 7) * 2);
                sum = fmaf(__half2float(hv), __ldg(W4 + k2), sum);
            }
            p.out[(size_t)h * BATCH + row0 + tid] = sum;
        }
        __syncthreads();
    }
}

extern "C" void kernel_launch(void* const* d_in, const int* in_sizes, int n_in,
                              void* d_out, int out_size) {
    (void)in_sizes; (void)n_in; (void)out_size;
    Params p;
    p.x    = (const float*)d_in[0];
    p.u    = (const float*)d_in[1];
    p.mixf = (const float*)d_in[2];
    p.P    = (const float*)d_in[3];
    for (int h = 0; h < 2; h++) {
        const int base = 4 + h * 8;
        p.W[h][0]  = (const float*)d_in[base + 0];
        p.Bb[h][0] = (const float*)d_in[base + 1];
        p.W[h][1]  = (const float*)d_in[base + 2];
        p.Bb[h][1] = (const float*)d_in[base + 3];
        p.W[h][2]  = (const float*)d_in[base + 4];
        p.Bb[h][2] = (const float*)d_in[base + 5];
        p.W4[h]    = (const float*)d_in[base + 6];
        p.b4[h]    = (const float*)d_in[base + 7];
        const int tbase = 20 + h * 6;
        p.tW[h][0] = (const float*)d_in[tbase + 0];
        p.tb[h][0] = (const float*)d_in[tbase + 1];
        p.tW[h][1] = (const float*)d_in[tbase + 2];
        p.tb[h][1] = (const float*)d_in[tbase + 3];
        p.tW[h][2] = (const float*)d_in[tbase + 4];
        p.tb[h][2] = (const float*)d_in[tbase + 5];
    }
    p.out = (float*)d_out;

    prep_kernel<<<(30 * 2048 + 960 + 255) / 256, 256>>>(p);
    cudaFuncSetAttribute(critic_main,
                         cudaFuncAttributeMaxDynamicSharedMemorySize, SMEM_BYTES);
    critic_main<<<NBLK, THREADS, SMEM_BYTES>>>(p);
}